// round 14
// baseline (speedup 1.0000x reference)
#include <cuda_runtime.h>
#include <cuda_bf16.h>
#include <cstdint>

// ---------------- problem constants ----------------
#define BATCH   64
#define FEAT    128
#define KDIM    2048
#define NDATA   100000
#define NSAMP   16385               // K+1
#define NPAIR   (BATCH * NSAMP)     // 1,048,640
#define NCE_T_INV (1.0f / 0.07f)
#define M_CONST (16384.0f / 100000.0f)
#define EPS_C   1e-7f

#define ESPLIT  32                  // embed k-splits per side (chunk 64)
#define KCH     64
#define RBLK    128                 // rows per logits tile
#define NTILE   ((NDATA + RBLK - 1) / RBLK)   // 782
#define SA      136                 // smem row stride (bf16 elems)

#define NBB     148                 // P2 blocks per bank
#define NB      (2 * NBB)           // 296 blocks = 148 SMs x occ 2
#define GSTRIDE (NB * 256)          // 75776 pairs/step (all blocks, both banks per pair)
#define GITER   14                  // ceil(NPAIR / GSTRIDE)

#define SMEM_DYN ((128 + 64) * SA * 2)   // 52224 B: Ws+Fs (P0) / Vs (P2)

// ---------------- device scratch (zero-init; reset each call) ----------------
__device__ float          g_partial[2][ESPLIT][FEAT * BATCH];   // [d*64+b]
__device__ float          g_hs[2][FEAT * BATCH];                // pre-norm h, [d*64+b]
__device__ float          g_nrm[2][BATCH];                      // sum of squares per b
__device__ uint16_t       g_Ei[(size_t)NDATA * BATCH * 2];      // bank-interleaved bf16 exp:
                                                                 // word (r*64+b) = [b0 | b1]
__device__ float          g_Zp[2][NB];
__device__ float          g_Lp[NB];
__device__ int            g_bars[5][8];

// ---------------- helpers ----------------
__device__ __forceinline__ void ldsm_x4(uint32_t* r, uint32_t addr) {
    asm volatile("ldmatrix.sync.aligned.m8n8.x4.shared.b16 {%0,%1,%2,%3}, [%4];"
                 : "=r"(r[0]), "=r"(r[1]), "=r"(r[2]), "=r"(r[3]) : "r"(addr));
}
__device__ __forceinline__ void mma_bf16(float* c, const uint32_t* a, uint32_t b0, uint32_t b1) {
    asm volatile("mma.sync.aligned.m16n8k16.row.col.f32.bf16.bf16.f32 "
                 "{%0,%1,%2,%3}, {%4,%5,%6,%7}, {%8,%9}, {%0,%1,%2,%3};"
                 : "+f"(c[0]), "+f"(c[1]), "+f"(c[2]), "+f"(c[3])
                 : "r"(a[0]), "r"(a[1]), "r"(a[2]), "r"(a[3]), "r"(b0), "r"(b1));
}
__device__ __forceinline__ uint32_t pack_bf2(float x, float y) {
    __nv_bfloat162 h2 = __floats2bfloat162_rn(x, y);
    return *reinterpret_cast<uint32_t*>(&h2);
}
__device__ __forceinline__ uint16_t bf16_bits(float x) {
    const __nv_bfloat16 h = __float2bfloat16(x);
    return *reinterpret_cast<const uint16_t*>(&h);
}
__device__ __forceinline__ uint32_t ld_u32_cg(const uint32_t* p) {
    uint32_t v;
    asm volatile("ld.global.cg.u32 %0, [%1];" : "=r"(v) : "l"(p));
    return v;
}
__device__ __forceinline__ float bf16lo(uint32_t w) {
    uint32_t f = (w & 0xFFFFu) << 16;
    return __uint_as_float(f);
}
__device__ __forceinline__ float bf16hi(uint32_t w) {
    uint32_t f = w & 0xFFFF0000u;
    return __uint_as_float(f);
}
__device__ __forceinline__ int bar_sum(int idx) {
    volatile int* s = g_bars[idx];
    int t = 0;
#pragma unroll
    for (int i = 0; i < 8; i++) t += s[i];
    return t;
}
__device__ __forceinline__ void gbar(int idx, int u) {
    __syncthreads();
    if (threadIdx.x == 0) {
        __threadfence();
        atomicAdd(&g_bars[idx][u & 7], 1);
        while (bar_sum(idx) < NB) __nanosleep(64);
    }
    __syncthreads();
}

// ================= the one kernel (occ 2) =================
__global__ __launch_bounds__(256, 2) void k_fused(
    const float* __restrict__ fs, const float* __restrict__ ft,
    const int*   __restrict__ samp,
    const float* __restrict__ ws, const float* __restrict__ bsv,
    const float* __restrict__ wt, const float* __restrict__ btv,
    const float* __restrict__ mem_v1, const float* __restrict__ mem_v2,
    float* __restrict__ out)
{
    extern __shared__ __align__(16) char dsm[];
    __shared__ float  s_red[8];
    __shared__ float  s_red2[8];
    __shared__ double s_dd[8];
    __shared__ float  s_z0, s_z1;
    __shared__ float  s_rinv[64];

    const int u    = blockIdx.x;
    const int tid  = threadIdx.x;
    const int lane = tid & 31, warp = tid >> 5;
    const int lr = lane & 7, q = lane >> 3;

    // ---------------- P0: embed GEMM via MMA, split-K (64 blocks) ----------------
    if (u < 2 * ESPLIT) {
        const int which = u >> 5;
        const int split = u & 31;
        const int k0 = split * KCH;
        const float* W = which ? wt : ws;
        const float* F = which ? ft : fs;

        uint16_t* Ws = reinterpret_cast<uint16_t*>(dsm);          // 128 x SA
        uint16_t* Fs = Ws + 128 * SA;                             // 64 x SA

#pragma unroll
        for (int j = 0; j < 8; j++) {
            const int i = tid + j * 256;
            const int row = i >> 4, c4 = i & 15;
            const float4 v = __ldg(reinterpret_cast<const float4*>(W + row * KDIM + k0) + c4);
            uint2 p;
            p.x = pack_bf2(v.x, v.y);
            p.y = pack_bf2(v.z, v.w);
            *reinterpret_cast<uint2*>(&Ws[row * SA + c4 * 4]) = p;
        }
#pragma unroll
        for (int j = 0; j < 4; j++) {
            const int i = tid + j * 256;
            const int row = i >> 4, c4 = i & 15;
            const float4 v = __ldg(reinterpret_cast<const float4*>(F + row * KDIM + k0) + c4);
            uint2 p;
            p.x = pack_bf2(v.x, v.y);
            p.y = pack_bf2(v.z, v.w);
            *reinterpret_cast<uint2*>(&Fs[row * SA + c4 * 4]) = p;
        }
        __syncthreads();

        const uint32_t a_base = (uint32_t)__cvta_generic_to_shared(Ws);
        const uint32_t b_base = (uint32_t)__cvta_generic_to_shared(Fs);
        const int mg = warp & 3, nh = warp >> 2;
        const int a_r = lr + ((q & 1) << 3), a_k = (q >> 1) << 3;
        const int b_r = lr + ((q >> 1) << 3), b_k = (q & 1) << 3;

        float acc[2][4][4];
#pragma unroll
        for (int mh = 0; mh < 2; mh++)
#pragma unroll
            for (int nf = 0; nf < 4; nf++)
#pragma unroll
                for (int e = 0; e < 4; e++) acc[mh][nf][e] = 0.f;

#pragma unroll
        for (int ks = 0; ks < 4; ks++) {
            const int kk = ks * 16;
            uint32_t a0[4], a1[4], bb0[4], bb1[4];
            ldsm_x4(a0, a_base + (uint32_t)((mg * 32 + a_r) * SA + kk + a_k) * 2u);
            ldsm_x4(a1, a_base + (uint32_t)((mg * 32 + 16 + a_r) * SA + kk + a_k) * 2u);
            ldsm_x4(bb0, b_base + (uint32_t)((nh * 32 + b_r) * SA + kk + b_k) * 2u);
            ldsm_x4(bb1, b_base + (uint32_t)((nh * 32 + 16 + b_r) * SA + kk + b_k) * 2u);
            mma_bf16(acc[0][0], a0, bb0[0], bb0[1]);
            mma_bf16(acc[0][1], a0, bb0[2], bb0[3]);
            mma_bf16(acc[0][2], a0, bb1[0], bb1[1]);
            mma_bf16(acc[0][3], a0, bb1[2], bb1[3]);
            mma_bf16(acc[1][0], a1, bb0[0], bb0[1]);
            mma_bf16(acc[1][1], a1, bb0[2], bb0[3]);
            mma_bf16(acc[1][2], a1, bb1[0], bb1[1]);
            mma_bf16(acc[1][3], a1, bb1[2], bb1[3]);
        }

        float* outp = g_partial[which][split];
        const int er = lane >> 2, ec = lane & 3;
#pragma unroll
        for (int mh = 0; mh < 2; mh++)
#pragma unroll
            for (int nf = 0; nf < 4; nf++) {
                const int rd = mg * 32 + mh * 16 + er;
                const int cb = nh * 32 + nf * 8 + ec * 2;
                float2 v0 = make_float2(acc[mh][nf][0], acc[mh][nf][1]);
                float2 v1 = make_float2(acc[mh][nf][2], acc[mh][nf][3]);
                *reinterpret_cast<float2*>(&outp[rd * BATCH + cb]) = v0;
                *reinterpret_cast<float2*>(&outp[(rd + 8) * BATCH + cb]) = v1;
            }
    }
    gbar(0, u);

    // ---------------- P1a: coalesced split-reduce + bias + sq-norm via REDG ----------------
    if (u < 64) {
        const int which = u >> 5;
        const int i = (u & 31) * 256 + tid;       // linear -> coalesced
        const int d = i >> 6, b = i & 63;
        const float* bias = which ? btv : bsv;
        float s = 0.f;
#pragma unroll
        for (int sp = 0; sp < ESPLIT; sp++)
            s += __ldcg(&g_partial[which][sp][i]);
        s += __ldg(&bias[d]);
        g_hs[which][i] = s;
        atomicAdd(&g_nrm[which][b], s * s);       // 32 distinct b per warp -> spread REDG
    }
    gbar(1, u);

    // ---------------- P2: dense logits GEMM + fused exp (front-batched) ----------------
    const int bank = (u >= NBB) ? 1 : 0;
    const int bx = u - bank * NBB;
    {
        const float* __restrict__ mem = bank ? mem_v1 : mem_v2;
        uint16_t* Vs = reinterpret_cast<uint16_t*>(dsm);          // 64 x SA

        // build Vs from g_hs + g_nrm (normalize + bf16 + transpose)
        if (tid < 64) s_rinv[tid] = rsqrtf(__ldcg(&g_nrm[bank][tid]));
        __syncthreads();
        {
            const float* hsrc = g_hs[bank];
#pragma unroll 8
            for (int it = 0; it < 32; it++) {
                const int i = it * 256 + tid;
                const int d = i >> 6, b = i & 63;
                const float v = __ldcg(&hsrc[i]) * s_rinv[b];
                const __nv_bfloat16 hv = __float2bfloat16(v);
                Vs[b * SA + d] = *reinterpret_cast<const uint16_t*>(&hv);
            }
        }
        __syncthreads();

        const uint32_t v_base = (uint32_t)__cvta_generic_to_shared(Vs);
        const int b_row = lr + ((q >> 1) << 3);
        const int b_kh  = (q & 1) << 3;

        for (int tile = bx; tile < NTILE; tile += NBB) {
            const int r_base = tile * RBLK;
            const int row0 = r_base + warp * 16 + (lane >> 2);
            const int row1 = row0 + 8;
            const int rc0 = row0 < NDATA ? row0 : NDATA - 1;
            const int rc1 = row1 < NDATA ? row1 : NDATA - 1;
            const float* p0 = mem + (size_t)rc0 * FEAT + (lane & 3) * 2;
            const float* p1 = mem + (size_t)rc1 * FEAT + (lane & 3) * 2;

            // front-batch: 32 independent LDG.64 per thread
            float2 rbuf[32];
#pragma unroll
            for (int ks = 0; ks < 8; ks++) {
                rbuf[ks * 4 + 0] = __ldcs(reinterpret_cast<const float2*>(p0 + ks * 16));
                rbuf[ks * 4 + 1] = __ldcs(reinterpret_cast<const float2*>(p1 + ks * 16));
                rbuf[ks * 4 + 2] = __ldcs(reinterpret_cast<const float2*>(p0 + ks * 16 + 8));
                rbuf[ks * 4 + 3] = __ldcs(reinterpret_cast<const float2*>(p1 + ks * 16 + 8));
            }

            float acc[8][4];
#pragma unroll
            for (int f = 0; f < 8; f++)
#pragma unroll
                for (int e = 0; e < 4; e++) acc[f][e] = 0.f;

#pragma unroll
            for (int ks = 0; ks < 8; ks++) {
                uint32_t a[4];
#pragma unroll
                for (int e = 0; e < 4; e++)
                    a[e] = pack_bf2(rbuf[ks * 4 + e].x, rbuf[ks * 4 + e].y);
                const int k0 = ks * 16;
#pragma unroll
                for (int nt = 0; nt < 4; nt++) {
                    uint32_t bb[4];
                    ldsm_x4(bb, v_base + (uint32_t)((nt * 16 + b_row) * SA + k0 + b_kh) * 2u);
                    mma_bf16(acc[nt * 2 + 0], a, bb[0], bb[1]);
                    mma_bf16(acc[nt * 2 + 1], a, bb[2], bb[3]);
                }
            }

            // epilogue: exp(logit/T) -> bf16, bank-interleaved E
            const int cbase = (lane & 3) * 2;
#pragma unroll
            for (int f = 0; f < 8; f++) {
                const int c = (f >> 1) * 16 + (f & 1) * 8 + cbase;
                if (row0 < NDATA) {
                    const size_t w = (size_t)row0 * BATCH + c;
                    g_Ei[w * 2 + bank]       = bf16_bits(__expf(acc[f][0] * NCE_T_INV));
                    g_Ei[(w + 1) * 2 + bank] = bf16_bits(__expf(acc[f][1] * NCE_T_INV));
                }
                if (row1 < NDATA) {
                    const size_t w = (size_t)row1 * BATCH + c;
                    g_Ei[w * 2 + bank]       = bf16_bits(__expf(acc[f][2] * NCE_T_INV));
                    g_Ei[(w + 1) * 2 + bank] = bf16_bits(__expf(acc[f][3] * NCE_T_INV));
                }
            }
        }
    }
    gbar(2, u);

    // ---------------- P3: pair-combined gather (BOTH banks per 4B load) + Z slots ----------------
    const int pbase = u * 256 + tid;
    float gv0[GITER], gv1[GITER];
    {
        const uint32_t* Ew = reinterpret_cast<const uint32_t*>(g_Ei);
#pragma unroll
        for (int i = 0; i < GITER; i++) {
            const int p = pbase + i * GSTRIDE;
            gv0[i] = 0.f; gv1[i] = 0.f;
            if (p < NPAIR) {
                const int s = __ldg(&samp[p]);
                const int b = p / NSAMP;
                const uint32_t w = ld_u32_cg(&Ew[(size_t)s * BATCH + b]);
                gv0[i] = bf16lo(w);
                gv1[i] = bf16hi(w);
            }
        }
        float ls0 = 0.f, ls1 = 0.f;
#pragma unroll
        for (int i = 0; i < GITER; i++) { ls0 += gv0[i]; ls1 += gv1[i]; }
#pragma unroll
        for (int o = 16; o; o >>= 1) {
            ls0 += __shfl_xor_sync(0xffffffffu, ls0, o);
            ls1 += __shfl_xor_sync(0xffffffffu, ls1, o);
        }
        if ((tid & 31) == 0) { s_red[tid >> 5] = ls0; s_red2[tid >> 5] = ls1; }
        __syncthreads();
        if (tid == 0) {
            double t0 = 0.0, t1 = 0.0;
#pragma unroll
            for (int i = 0; i < 8; i++) { t0 += (double)s_red[i]; t1 += (double)s_red2[i]; }
            g_Zp[0][u] = (float)t0;
            g_Zp[1][u] = (float)t1;
        }
    }
    gbar(3, u);

    // each block reduces ALL 296 Z slots for both banks (deterministic order)
    {
        float z0 = (tid < NB) ? *(volatile float*)&g_Zp[0][tid] : 0.f;
        float z1 = (tid < NB) ? *(volatile float*)&g_Zp[1][tid] : 0.f;
        if (tid + 256 < NB) {
            z0 += *(volatile float*)&g_Zp[0][tid + 256];
            z1 += *(volatile float*)&g_Zp[1][tid + 256];
        }
#pragma unroll
        for (int o = 16; o; o >>= 1) {
            z0 += __shfl_xor_sync(0xffffffffu, z0, o);
            z1 += __shfl_xor_sync(0xffffffffu, z1, o);
        }
        if (lane == 0) { s_red[warp] = z0; s_red2[warp] = z1; }
        __syncthreads();
        if (tid == 0) {
            float t0 = 0.f, t1 = 0.f;
#pragma unroll
            for (int i = 0; i < 8; i++) { t0 += s_red[i]; t1 += s_red2[i]; }
            s_z0 = (float)((double)t0 * ((double)NDATA / (double)NPAIR));
            s_z1 = (float)((double)t1 * ((double)NDATA / (double)NPAIR));
        }
        __syncthreads();
    }

    // ---------------- P4: loss for both banks from registers (batched logs) ----------------
    {
        const float zi0 = 1.0f / s_z0;
        const float zi1 = 1.0f / s_z1;
        float lsum = 0.f;
        float pn = 1.f, pd = 1.f;
#pragma unroll
        for (int i = 0; i < GITER; i++) {
            const int p = pbase + i * GSTRIDE;
            if (p < NPAIR) {
                const int b = p / NSAMP;
                const bool pos = (p - b * NSAMP) == 0;
                const float x0 = gv0[i] * zi0;
                const float x1 = gv1[i] * zi1;
                pn *= pos ? x0 : M_CONST;
                pd *= x0 + M_CONST + EPS_C;
                pn *= pos ? x1 : M_CONST;
                pd *= x1 + M_CONST + EPS_C;
            }
            if (i == 6 || i == GITER - 1) {   // batches of 14 terms
                lsum += __logf(pn / pd);
                pn = 1.f; pd = 1.f;
            }
        }
#pragma unroll
        for (int o = 16; o; o >>= 1) lsum += __shfl_xor_sync(0xffffffffu, lsum, o);
        __syncthreads();
        if ((tid & 31) == 0) s_red[tid >> 5] = lsum;
        __syncthreads();
        if (tid == 0) {
            double tot = 0.0;
#pragma unroll
            for (int i = 0; i < 8; i++) tot += (double)s_red[i];
            g_Lp[u] = (float)tot;
            __threadfence();
            atomicAdd(&g_bars[4][u & 7], 1);
        }
    }

    // ---------------- block 0: finalize + reset ----------------
    if (u == 0) {
        if (tid == 0) {
            while (bar_sum(4) < NB) __nanosleep(64);
        }
        __syncthreads();
        double s = 0.0;
        if (tid < NB) s = (double)*(volatile float*)&g_Lp[tid];
        if (tid + 256 < NB) s += (double)*(volatile float*)&g_Lp[tid + 256];
#pragma unroll
        for (int o = 16; o; o >>= 1) s += __shfl_down_sync(0xffffffffu, s, o);
        if (lane == 0) s_dd[warp] = s;
        __syncthreads();
        if (tid == 0) {
            double t = 0.0;
#pragma unroll
            for (int i = 0; i < 8; i++) t += s_dd[i];
            out[0] = (float)(-t / (double)BATCH);
        }
        // reset barrier shards + norm accumulators for the next graph replay
        if (tid < 40) g_bars[tid >> 3][tid & 7] = 0;
        if (tid < 128) g_nrm[tid >> 6][tid & 63] = 0.f;
        __threadfence();
    }
}

// ---------------- launcher ----------------
extern "C" void kernel_launch(void* const* d_in, const int* in_sizes, int n_in,
                              void* d_out, int out_size) {
    const float* feat_s     = (const float*)d_in[0];
    const float* feat_t     = (const float*)d_in[1];
    // d_in[2] = idx (unused; positives already in sample_idx[:,0])
    const int*   sample_idx = (const int*)d_in[3];
    const float* w_s        = (const float*)d_in[4];
    const float* b_s        = (const float*)d_in[5];
    const float* w_t        = (const float*)d_in[6];
    const float* b_t        = (const float*)d_in[7];
    const float* mem_v1     = (const float*)d_in[8];
    const float* mem_v2     = (const float*)d_in[9];
    float* out = (float*)d_out;

    cudaFuncSetAttribute(k_fused, cudaFuncAttributeMaxDynamicSharedMemorySize, SMEM_DYN);
    k_fused<<<NB, 256, SMEM_DYN>>>(feat_s, feat_t, sample_idx,
                                   w_s, b_s, w_t, b_t, mem_v1, mem_v2, out);
}

// round 15
// speedup vs baseline: 1.1389x; 1.1389x over previous
#include <cuda_runtime.h>
#include <cuda_bf16.h>
#include <cstdint>

// ---------------- problem constants ----------------
#define BATCH   64
#define FEAT    128
#define KDIM    2048
#define NDATA   100000
#define NSAMP   16385               // K+1
#define NPAIR   (BATCH * NSAMP)     // 1,048,640
#define NCE_T_INV (1.0f / 0.07f)
#define M_CONST (16384.0f / 100000.0f)
#define EPS_C   1e-7f

#define ESPLIT  32                  // embed k-splits per side (chunk 64)
#define KCH     64
#define RBLK    128                 // rows per logits tile
#define NTILE   ((NDATA + RBLK - 1) / RBLK)   // 782
#define SA      136                 // smem row stride (bf16 elems)

#define NBB     148                 // blocks per bank
#define NB      (2 * NBB)           // 296 blocks = 148 SMs x occ 2
#define GSTRIDE (NBB * 256)         // 37888
#define GITER   28                  // ceil(NPAIR / GSTRIDE)

#define SMEM_DYN ((128 + 64) * SA * 2)   // 52224 B: Ws+Fs (P0) / Vs (P2)

// ---------------- device scratch (zero-init; reset each call) ----------------
__device__ float          g_partial[2][ESPLIT][FEAT * BATCH];   // [d*64+b]
__device__ float          g_hs[2][FEAT * BATCH];                // pre-norm h, [d*64+b]
__device__ float          g_nrm[2][BATCH];                      // sum of squares per b
__device__ __nv_bfloat16  g_E[2][(size_t)NDATA * BATCH];        // bf16 exp(logit), [r][b]
__device__ float          g_Zp[2][NBB];
__device__ float          g_Lp[NB];
__device__ int            g_bars[5][8];

// ---------------- helpers ----------------
__device__ __forceinline__ void ldsm_x4(uint32_t* r, uint32_t addr) {
    asm volatile("ldmatrix.sync.aligned.m8n8.x4.shared.b16 {%0,%1,%2,%3}, [%4];"
                 : "=r"(r[0]), "=r"(r[1]), "=r"(r[2]), "=r"(r[3]) : "r"(addr));
}
__device__ __forceinline__ void mma_bf16(float* c, const uint32_t* a, uint32_t b0, uint32_t b1) {
    asm volatile("mma.sync.aligned.m16n8k16.row.col.f32.bf16.bf16.f32 "
                 "{%0,%1,%2,%3}, {%4,%5,%6,%7}, {%8,%9}, {%0,%1,%2,%3};"
                 : "+f"(c[0]), "+f"(c[1]), "+f"(c[2]), "+f"(c[3])
                 : "r"(a[0]), "r"(a[1]), "r"(a[2]), "r"(a[3]), "r"(b0), "r"(b1));
}
__device__ __forceinline__ uint32_t pack_bf2(float x, float y) {
    __nv_bfloat162 h2 = __floats2bfloat162_rn(x, y);
    return *reinterpret_cast<uint32_t*>(&h2);
}
__device__ __forceinline__ float ld_e_cg(const __nv_bfloat16* p) {
    unsigned short v;
    asm volatile("ld.global.cg.u16 %0, [%1];" : "=h"(v) : "l"(p));
    __nv_bfloat16 b;
    *reinterpret_cast<unsigned short*>(&b) = v;
    return __bfloat162float(b);
}
__device__ __forceinline__ int bar_sum(int idx) {
    volatile int* s = g_bars[idx];
    int t = 0;
#pragma unroll
    for (int i = 0; i < 8; i++) t += s[i];
    return t;
}
__device__ __forceinline__ void gbar(int idx, int u) {
    __syncthreads();
    if (threadIdx.x == 0) {
        __threadfence();
        atomicAdd(&g_bars[idx][u & 7], 1);
        while (bar_sum(idx) < NB) __nanosleep(64);
    }
    __syncthreads();
}

// ================= the one kernel (occ 2) =================
__global__ __launch_bounds__(256, 2) void k_fused(
    const float* __restrict__ fs, const float* __restrict__ ft,
    const int*   __restrict__ samp,
    const float* __restrict__ ws, const float* __restrict__ bsv,
    const float* __restrict__ wt, const float* __restrict__ btv,
    const float* __restrict__ mem_v1, const float* __restrict__ mem_v2,
    float* __restrict__ out)
{
    extern __shared__ __align__(16) char dsm[];
    __shared__ float  s_red[8];
    __shared__ double s_dd[8];
    __shared__ float  s_z;
    __shared__ float  s_rinv[64];

    const int u    = blockIdx.x;
    const int tid  = threadIdx.x;
    const int lane = tid & 31, warp = tid >> 5;
    const int lr = lane & 7, q = lane >> 3;

    // ---------------- P0: embed GEMM via MMA, split-K (64 blocks) ----------------
    if (u < 2 * ESPLIT) {
        const int which = u >> 5;
        const int split = u & 31;
        const int k0 = split * KCH;
        const float* W = which ? wt : ws;
        const float* F = which ? ft : fs;

        uint16_t* Ws = reinterpret_cast<uint16_t*>(dsm);          // 128 x SA
        uint16_t* Fs = Ws + 128 * SA;                             // 64 x SA

#pragma unroll
        for (int j = 0; j < 8; j++) {
            const int i = tid + j * 256;
            const int row = i >> 4, c4 = i & 15;
            const float4 v = __ldg(reinterpret_cast<const float4*>(W + row * KDIM + k0) + c4);
            uint2 p;
            p.x = pack_bf2(v.x, v.y);
            p.y = pack_bf2(v.z, v.w);
            *reinterpret_cast<uint2*>(&Ws[row * SA + c4 * 4]) = p;
        }
#pragma unroll
        for (int j = 0; j < 4; j++) {
            const int i = tid + j * 256;
            const int row = i >> 4, c4 = i & 15;
            const float4 v = __ldg(reinterpret_cast<const float4*>(F + row * KDIM + k0) + c4);
            uint2 p;
            p.x = pack_bf2(v.x, v.y);
            p.y = pack_bf2(v.z, v.w);
            *reinterpret_cast<uint2*>(&Fs[row * SA + c4 * 4]) = p;
        }
        __syncthreads();

        const uint32_t a_base = (uint32_t)__cvta_generic_to_shared(Ws);
        const uint32_t b_base = (uint32_t)__cvta_generic_to_shared(Fs);
        const int mg = warp & 3, nh = warp >> 2;
        const int a_r = lr + ((q & 1) << 3), a_k = (q >> 1) << 3;
        const int b_r = lr + ((q >> 1) << 3), b_k = (q & 1) << 3;

        float acc[2][4][4];
#pragma unroll
        for (int mh = 0; mh < 2; mh++)
#pragma unroll
            for (int nf = 0; nf < 4; nf++)
#pragma unroll
                for (int e = 0; e < 4; e++) acc[mh][nf][e] = 0.f;

#pragma unroll
        for (int ks = 0; ks < 4; ks++) {
            const int kk = ks * 16;
            uint32_t a0[4], a1[4], bb0[4], bb1[4];
            ldsm_x4(a0, a_base + (uint32_t)((mg * 32 + a_r) * SA + kk + a_k) * 2u);
            ldsm_x4(a1, a_base + (uint32_t)((mg * 32 + 16 + a_r) * SA + kk + a_k) * 2u);
            ldsm_x4(bb0, b_base + (uint32_t)((nh * 32 + b_r) * SA + kk + b_k) * 2u);
            ldsm_x4(bb1, b_base + (uint32_t)((nh * 32 + 16 + b_r) * SA + kk + b_k) * 2u);
            mma_bf16(acc[0][0], a0, bb0[0], bb0[1]);
            mma_bf16(acc[0][1], a0, bb0[2], bb0[3]);
            mma_bf16(acc[0][2], a0, bb1[0], bb1[1]);
            mma_bf16(acc[0][3], a0, bb1[2], bb1[3]);
            mma_bf16(acc[1][0], a1, bb0[0], bb0[1]);
            mma_bf16(acc[1][1], a1, bb0[2], bb0[3]);
            mma_bf16(acc[1][2], a1, bb1[0], bb1[1]);
            mma_bf16(acc[1][3], a1, bb1[2], bb1[3]);
        }

        float* outp = g_partial[which][split];
        const int er = lane >> 2, ec = lane & 3;
#pragma unroll
        for (int mh = 0; mh < 2; mh++)
#pragma unroll
            for (int nf = 0; nf < 4; nf++) {
                const int rd = mg * 32 + mh * 16 + er;
                const int cb = nh * 32 + nf * 8 + ec * 2;
                float2 v0 = make_float2(acc[mh][nf][0], acc[mh][nf][1]);
                float2 v1 = make_float2(acc[mh][nf][2], acc[mh][nf][3]);
                *reinterpret_cast<float2*>(&outp[rd * BATCH + cb]) = v0;
                *reinterpret_cast<float2*>(&outp[(rd + 8) * BATCH + cb]) = v1;
            }
    }
    gbar(0, u);

    // ---------------- P1a: coalesced split-reduce + bias + sq-norm via REDG ----------------
    if (u < 64) {
        const int which = u >> 5;
        const int i = (u & 31) * 256 + tid;       // linear -> coalesced
        const int d = i >> 6, b = i & 63;
        const float* bias = which ? btv : bsv;
        float s = 0.f;
#pragma unroll
        for (int sp = 0; sp < ESPLIT; sp++)
            s += __ldcg(&g_partial[which][sp][i]);
        s += __ldg(&bias[d]);
        g_hs[which][i] = s;
        atomicAdd(&g_nrm[which][b], s * s);       // 32 distinct b per warp -> spread REDG
    }
    gbar(1, u);

    // ---------------- P2: dense logits GEMM + fused exp, cross-tile modulo pipeline ----------------
    const int bank = (u >= NBB) ? 1 : 0;
    const int bx = u - bank * NBB;
    {
        const float* __restrict__ mem = bank ? mem_v1 : mem_v2;
        uint16_t* Vs = reinterpret_cast<uint16_t*>(dsm);          // 64 x SA

        // build Vs from g_hs + g_nrm (normalize + bf16 + transpose)
        if (tid < 64) s_rinv[tid] = rsqrtf(__ldcg(&g_nrm[bank][tid]));
        __syncthreads();
        {
            const float* hsrc = g_hs[bank];
#pragma unroll 8
            for (int it = 0; it < 32; it++) {
                const int i = it * 256 + tid;
                const int d = i >> 6, b = i & 63;
                const float v = __ldcg(&hsrc[i]) * s_rinv[b];
                const __nv_bfloat16 hv = __float2bfloat16(v);
                Vs[b * SA + d] = *reinterpret_cast<const uint16_t*>(&hv);
            }
        }
        __syncthreads();

        const uint32_t v_base = (uint32_t)__cvta_generic_to_shared(Vs);
        const int b_row = lr + ((q >> 1) << 3);
        const int b_kh  = (q & 1) << 3;
        const int lrow = warp * 16 + (lane >> 2);     // local row of fragment row0
        const int coff = (lane & 3) * 2;              // column offset within row
        uint32_t* Eb = reinterpret_cast<uint32_t*>(g_E[bank]);

        // ---- prologue: load tile bx into rbuf (full burst, once) ----
        float2 rbuf[32];
        int row0 = bx * RBLK + lrow;
        int row1 = row0 + 8;
        {
            const int c0 = row0 < NDATA ? row0 : NDATA - 1;
            const int c1 = row1 < NDATA ? row1 : NDATA - 1;
            const float* p0 = mem + (size_t)c0 * FEAT + coff;
            const float* p1 = mem + (size_t)c1 * FEAT + coff;
#pragma unroll
            for (int ks = 0; ks < 8; ks++) {
                rbuf[ks * 4 + 0] = __ldcs(reinterpret_cast<const float2*>(p0 + ks * 16));
                rbuf[ks * 4 + 1] = __ldcs(reinterpret_cast<const float2*>(p1 + ks * 16));
                rbuf[ks * 4 + 2] = __ldcs(reinterpret_cast<const float2*>(p0 + ks * 16 + 8));
                rbuf[ks * 4 + 3] = __ldcs(reinterpret_cast<const float2*>(p1 + ks * 16 + 8));
            }
        }

        for (int tile = bx; tile < NTILE; tile += NBB) {
            const bool hn = (tile + NBB) < NTILE;
            // next tile's row pointers (loads interleaved into this tile's k-loop)
            int nr0 = (tile + NBB) * RBLK + lrow;
            int nr1 = nr0 + 8;
            const int nc0 = nr0 < NDATA ? nr0 : NDATA - 1;
            const int nc1 = nr1 < NDATA ? nr1 : NDATA - 1;
            const float* n0 = mem + (size_t)nc0 * FEAT + coff;
            const float* n1 = mem + (size_t)nc1 * FEAT + coff;

            float acc[8][4];
#pragma unroll
            for (int f = 0; f < 8; f++)
#pragma unroll
                for (int e = 0; e < 4; e++) acc[f][e] = 0.f;

#pragma unroll
            for (int ks = 0; ks < 8; ks++) {
                // consume current tile's slot group
                uint32_t a[4];
#pragma unroll
                for (int e = 0; e < 4; e++)
                    a[e] = pack_bf2(rbuf[ks * 4 + e].x, rbuf[ks * 4 + e].y);
                // refill the just-freed slots with NEXT tile's data (modulo schedule)
                if (hn) {
                    rbuf[ks * 4 + 0] = __ldcs(reinterpret_cast<const float2*>(n0 + ks * 16));
                    rbuf[ks * 4 + 1] = __ldcs(reinterpret_cast<const float2*>(n1 + ks * 16));
                    rbuf[ks * 4 + 2] = __ldcs(reinterpret_cast<const float2*>(n0 + ks * 16 + 8));
                    rbuf[ks * 4 + 3] = __ldcs(reinterpret_cast<const float2*>(n1 + ks * 16 + 8));
                }
                const int k0 = ks * 16;
#pragma unroll
                for (int nt = 0; nt < 4; nt++) {
                    uint32_t bb[4];
                    ldsm_x4(bb, v_base + (uint32_t)((nt * 16 + b_row) * SA + k0 + b_kh) * 2u);
                    mma_bf16(acc[nt * 2 + 0], a, bb[0], bb[1]);
                    mma_bf16(acc[nt * 2 + 1], a, bb[2], bb[3]);
                }
            }

            // epilogue: exp(logit/T) -> bf16 E[r][b] for CURRENT tile rows
#pragma unroll
            for (int f = 0; f < 8; f++) {
                const int c = (f >> 1) * 16 + (f & 1) * 8 + coff;
                if (row0 < NDATA)
                    Eb[(size_t)row0 * (BATCH / 2) + (c >> 1)] =
                        pack_bf2(__expf(acc[f][0] * NCE_T_INV), __expf(acc[f][1] * NCE_T_INV));
                if (row1 < NDATA)
                    Eb[(size_t)row1 * (BATCH / 2) + (c >> 1)] =
                        pack_bf2(__expf(acc[f][2] * NCE_T_INV), __expf(acc[f][3] * NCE_T_INV));
            }
            row0 = nr0;
            row1 = nr1;
        }
    }
    gbar(2, u);

    // ---------------- P3: gather into registers + per-block Z slot ----------------
    const int pbase = bx * 256 + tid;
    float gv[GITER];
    {
#pragma unroll
        for (int i = 0; i < GITER; i++) {
            const int p = pbase + i * GSTRIDE;
            gv[i] = 0.f;
            if (p < NPAIR) {
                const int s = __ldg(&samp[p]);
                const int b = p / NSAMP;
                gv[i] = ld_e_cg(&g_E[bank][(size_t)s * BATCH + b]);
            }
        }
        float lsum = 0.f;
#pragma unroll
        for (int i = 0; i < GITER; i++) lsum += gv[i];
#pragma unroll
        for (int o = 16; o; o >>= 1) lsum += __shfl_xor_sync(0xffffffffu, lsum, o);
        if ((tid & 31) == 0) s_red[tid >> 5] = lsum;
        __syncthreads();
        if (tid == 0) {
            double tot = 0.0;
#pragma unroll
            for (int i = 0; i < 8; i++) tot += (double)s_red[i];
            g_Zp[bank][bx] = (float)tot;
        }
    }
    gbar(3, u);

    // each block reduces its bank's Z slots
    {
        float zv = (tid < NBB) ? *(volatile float*)&g_Zp[bank][tid] : 0.f;
#pragma unroll
        for (int o = 16; o; o >>= 1) zv += __shfl_xor_sync(0xffffffffu, zv, o);
        if (lane == 0) s_red[warp] = zv;
        __syncthreads();
        if (tid == 0) {
            float zt = 0.f;
#pragma unroll
            for (int i = 0; i < 8; i++) zt += s_red[i];
            s_z = (float)((double)zt * ((double)NDATA / (double)NPAIR));
        }
        __syncthreads();
    }

    // ---------------- P4: loss from registers (batched logs) ----------------
    {
        const float zinv = 1.0f / s_z;
        float lsum = 0.f;
        float pn = 1.f, pd = 1.f;
#pragma unroll
        for (int i = 0; i < GITER; i++) {
            const int p = pbase + i * GSTRIDE;
            if (p < NPAIR) {
                const float x = gv[i] * zinv;
                const int b = p / NSAMP;
                const bool pos = (p - b * NSAMP) == 0;
                pn *= pos ? x : M_CONST;
                pd *= x + M_CONST + EPS_C;
            }
            if (i == 13 || i == GITER - 1) {
                lsum += __logf(pn / pd);
                pn = 1.f; pd = 1.f;
            }
        }
#pragma unroll
        for (int o = 16; o; o >>= 1) lsum += __shfl_xor_sync(0xffffffffu, lsum, o);
        __syncthreads();
        if ((tid & 31) == 0) s_red[tid >> 5] = lsum;
        __syncthreads();
        if (tid == 0) {
            double tot = 0.0;
#pragma unroll
            for (int i = 0; i < 8; i++) tot += (double)s_red[i];
            g_Lp[u] = (float)tot;
            __threadfence();
            atomicAdd(&g_bars[4][u & 7], 1);
        }
    }

    // ---------------- block 0: finalize + reset ----------------
    if (u == 0) {
        if (tid == 0) {
            while (bar_sum(4) < NB) __nanosleep(64);
        }
        __syncthreads();
        double s = 0.0;
        if (tid < NB) s = (double)*(volatile float*)&g_Lp[tid];
        if (tid + 256 < NB) s += (double)*(volatile float*)&g_Lp[tid + 256];
#pragma unroll
        for (int o = 16; o; o >>= 1) s += __shfl_down_sync(0xffffffffu, s, o);
        if (lane == 0) s_dd[warp] = s;
        __syncthreads();
        if (tid == 0) {
            double t = 0.0;
#pragma unroll
            for (int i = 0; i < 8; i++) t += s_dd[i];
            out[0] = (float)(-t / (double)BATCH);
        }
        // reset barrier shards + norm accumulators for the next graph replay
        if (tid < 40) g_bars[tid >> 3][tid & 7] = 0;
        if (tid < 128) g_nrm[tid >> 6][tid & 63] = 0.f;
        __threadfence();
    }
}

// ---------------- launcher ----------------
extern "C" void kernel_launch(void* const* d_in, const int* in_sizes, int n_in,
                              void* d_out, int out_size) {
    const float* feat_s     = (const float*)d_in[0];
    const float* feat_t     = (const float*)d_in[1];
    // d_in[2] = idx (unused; positives already in sample_idx[:,0])
    const int*   sample_idx = (const int*)d_in[3];
    const float* w_s        = (const float*)d_in[4];
    const float* b_s        = (const float*)d_in[5];
    const float* w_t        = (const float*)d_in[6];
    const float* b_t        = (const float*)d_in[7];
    const float* mem_v1     = (const float*)d_in[8];
    const float* mem_v2     = (const float*)d_in[9];
    float* out = (float*)d_out;

    cudaFuncSetAttribute(k_fused, cudaFuncAttributeMaxDynamicSharedMemorySize, SMEM_DYN);
    k_fused<<<NB, 256, SMEM_DYN>>>(feat_s, feat_t, sample_idx,
                                   w_s, b_s, w_t, b_t, mem_v1, mem_v2, out);
}

// round 16
// speedup vs baseline: 1.1711x; 1.0282x over previous
#include <cuda_runtime.h>
#include <cuda_bf16.h>
#include <cstdint>

// ---------------- problem constants ----------------
#define BATCH   64
#define FEAT    128
#define KDIM    2048
#define NDATA   100000
#define NSAMP   16385               // K+1
#define NPAIR   (BATCH * NSAMP)     // 1,048,640
#define NCE_T_INV (1.0f / 0.07f)
#define M_CONST (16384.0f / 100000.0f)
#define EPS_C   1e-7f

#define ESPLIT  32                  // embed k-splits per side (chunk 64)
#define KCH     64
#define RBLK    128                 // rows per logits tile
#define NTILE   ((NDATA + RBLK - 1) / RBLK)   // 782
#define SA      136                 // smem row stride (bf16 elems)

#define NBB     148                 // blocks per bank
#define NB      (2 * NBB)           // 296 blocks = 148 SMs x occ 2
#define GSTRIDE (NBB * 256)         // 37888
#define GITER   28                  // ceil(NPAIR / GSTRIDE)

#define ABUF    (RBLK * SA * 2)                 // 34816 B per A buffer (bf16)
#define VS_OFF  (2 * ABUF)                      // 69632
#define SMEM_DYN (VS_OFF + BATCH * SA * 2)      // 87040 (P0 needs 52224, fits)

// ---------------- device scratch (zero-init; reset each call) ----------------
__device__ float          g_partial[2][ESPLIT][FEAT * BATCH];   // [d*64+b]
__device__ float          g_hs[2][FEAT * BATCH];                // pre-norm h, [d*64+b]
__device__ float          g_nrm[2][BATCH];                      // sum of squares per b
__device__ __nv_bfloat16  g_E[2][(size_t)NDATA * BATCH];        // bf16 exp(logit), [r][b]
__device__ float          g_Zp[2][NBB];
__device__ float          g_Lp[NB];
__device__ int            g_bars[5][8];

// ---------------- helpers ----------------
__device__ __forceinline__ void ldsm_x4(uint32_t* r, uint32_t addr) {
    asm volatile("ldmatrix.sync.aligned.m8n8.x4.shared.b16 {%0,%1,%2,%3}, [%4];"
                 : "=r"(r[0]), "=r"(r[1]), "=r"(r[2]), "=r"(r[3]) : "r"(addr));
}
__device__ __forceinline__ void mma_bf16(float* c, const uint32_t* a, uint32_t b0, uint32_t b1) {
    asm volatile("mma.sync.aligned.m16n8k16.row.col.f32.bf16.bf16.f32 "
                 "{%0,%1,%2,%3}, {%4,%5,%6,%7}, {%8,%9}, {%0,%1,%2,%3};"
                 : "+f"(c[0]), "+f"(c[1]), "+f"(c[2]), "+f"(c[3])
                 : "r"(a[0]), "r"(a[1]), "r"(a[2]), "r"(a[3]), "r"(b0), "r"(b1));
}
__device__ __forceinline__ uint32_t pack_bf2(float x, float y) {
    __nv_bfloat162 h2 = __floats2bfloat162_rn(x, y);
    return *reinterpret_cast<uint32_t*>(&h2);
}
__device__ __forceinline__ float ld_e_cg(const __nv_bfloat16* p) {
    unsigned short v;
    asm volatile("ld.global.cg.u16 %0, [%1];" : "=h"(v) : "l"(p));
    __nv_bfloat16 b;
    *reinterpret_cast<unsigned short*>(&b) = v;
    return __bfloat162float(b);
}
__device__ __forceinline__ int bar_sum(int idx) {
    volatile int* s = g_bars[idx];
    int t = 0;
#pragma unroll
    for (int i = 0; i < 8; i++) t += s[i];
    return t;
}
__device__ __forceinline__ void gbar(int idx, int u) {
    __syncthreads();
    if (threadIdx.x == 0) {
        __threadfence();
        atomicAdd(&g_bars[idx][u & 7], 1);
        while (bar_sum(idx) < NB) __nanosleep(64);
    }
    __syncthreads();
}

// ================= the one kernel (occ 2) =================
__global__ __launch_bounds__(256, 2) void k_fused(
    const float* __restrict__ fs, const float* __restrict__ ft,
    const int*   __restrict__ samp,
    const float* __restrict__ ws, const float* __restrict__ bsv,
    const float* __restrict__ wt, const float* __restrict__ btv,
    const float* __restrict__ mem_v1, const float* __restrict__ mem_v2,
    float* __restrict__ out)
{
    extern __shared__ __align__(16) char dsm[];
    __shared__ float  s_red[8];
    __shared__ double s_dd[8];
    __shared__ float  s_z;
    __shared__ float  s_rinv[64];

    const int u    = blockIdx.x;
    const int tid  = threadIdx.x;
    const int lane = tid & 31, warp = tid >> 5;
    const int lr = lane & 7, q = lane >> 3;

    // ---------------- P0: embed GEMM via MMA, split-K (64 blocks) ----------------
    if (u < 2 * ESPLIT) {
        const int which = u >> 5;
        const int split = u & 31;
        const int k0 = split * KCH;
        const float* W = which ? wt : ws;
        const float* F = which ? ft : fs;

        uint16_t* Ws = reinterpret_cast<uint16_t*>(dsm);          // 128 x SA
        uint16_t* Fs = Ws + 128 * SA;                             // 64 x SA

#pragma unroll
        for (int j = 0; j < 8; j++) {
            const int i = tid + j * 256;
            const int row = i >> 4, c4 = i & 15;
            const float4 v = __ldg(reinterpret_cast<const float4*>(W + row * KDIM + k0) + c4);
            uint2 p;
            p.x = pack_bf2(v.x, v.y);
            p.y = pack_bf2(v.z, v.w);
            *reinterpret_cast<uint2*>(&Ws[row * SA + c4 * 4]) = p;
        }
#pragma unroll
        for (int j = 0; j < 4; j++) {
            const int i = tid + j * 256;
            const int row = i >> 4, c4 = i & 15;
            const float4 v = __ldg(reinterpret_cast<const float4*>(F + row * KDIM + k0) + c4);
            uint2 p;
            p.x = pack_bf2(v.x, v.y);
            p.y = pack_bf2(v.z, v.w);
            *reinterpret_cast<uint2*>(&Fs[row * SA + c4 * 4]) = p;
        }
        __syncthreads();

        const uint32_t a_base = (uint32_t)__cvta_generic_to_shared(Ws);
        const uint32_t b_base = (uint32_t)__cvta_generic_to_shared(Fs);
        const int mg = warp & 3, nh = warp >> 2;
        const int a_r = lr + ((q & 1) << 3), a_k = (q >> 1) << 3;
        const int b_r = lr + ((q >> 1) << 3), b_k = (q & 1) << 3;

        float acc[2][4][4];
#pragma unroll
        for (int mh = 0; mh < 2; mh++)
#pragma unroll
            for (int nf = 0; nf < 4; nf++)
#pragma unroll
                for (int e = 0; e < 4; e++) acc[mh][nf][e] = 0.f;

#pragma unroll
        for (int ks = 0; ks < 4; ks++) {
            const int kk = ks * 16;
            uint32_t a0[4], a1[4], bb0[4], bb1[4];
            ldsm_x4(a0, a_base + (uint32_t)((mg * 32 + a_r) * SA + kk + a_k) * 2u);
            ldsm_x4(a1, a_base + (uint32_t)((mg * 32 + 16 + a_r) * SA + kk + a_k) * 2u);
            ldsm_x4(bb0, b_base + (uint32_t)((nh * 32 + b_r) * SA + kk + b_k) * 2u);
            ldsm_x4(bb1, b_base + (uint32_t)((nh * 32 + 16 + b_r) * SA + kk + b_k) * 2u);
            mma_bf16(acc[0][0], a0, bb0[0], bb0[1]);
            mma_bf16(acc[0][1], a0, bb0[2], bb0[3]);
            mma_bf16(acc[0][2], a0, bb1[0], bb1[1]);
            mma_bf16(acc[0][3], a0, bb1[2], bb1[3]);
            mma_bf16(acc[1][0], a1, bb0[0], bb0[1]);
            mma_bf16(acc[1][1], a1, bb0[2], bb0[3]);
            mma_bf16(acc[1][2], a1, bb1[0], bb1[1]);
            mma_bf16(acc[1][3], a1, bb1[2], bb1[3]);
        }

        float* outp = g_partial[which][split];
        const int er = lane >> 2, ec = lane & 3;
#pragma unroll
        for (int mh = 0; mh < 2; mh++)
#pragma unroll
            for (int nf = 0; nf < 4; nf++) {
                const int rd = mg * 32 + mh * 16 + er;
                const int cb = nh * 32 + nf * 8 + ec * 2;
                float2 v0 = make_float2(acc[mh][nf][0], acc[mh][nf][1]);
                float2 v1 = make_float2(acc[mh][nf][2], acc[mh][nf][3]);
                *reinterpret_cast<float2*>(&outp[rd * BATCH + cb]) = v0;
                *reinterpret_cast<float2*>(&outp[(rd + 8) * BATCH + cb]) = v1;
            }
    }
    gbar(0, u);

    // ---------------- P1a: coalesced split-reduce + bias + sq-norm via REDG ----------------
    if (u < 64) {
        const int which = u >> 5;
        const int i = (u & 31) * 256 + tid;       // linear -> coalesced
        const int d = i >> 6, b = i & 63;
        const float* bias = which ? btv : bsv;
        float s = 0.f;
#pragma unroll
        for (int sp = 0; sp < ESPLIT; sp++)
            s += __ldcg(&g_partial[which][sp][i]);
        s += __ldg(&bias[d]);
        g_hs[which][i] = s;
        atomicAdd(&g_nrm[which][b], s * s);       // 32 distinct b per warp -> spread REDG
    }
    gbar(1, u);

    // ---------------- P2: coalesced-LDG + smem-ldmatrix bf16 GEMM + fused exp ----------------
    const int bank = (u >= NBB) ? 1 : 0;
    const int bx = u - bank * NBB;
    {
        const float* __restrict__ mem = bank ? mem_v1 : mem_v2;
        uint16_t* Ab0 = reinterpret_cast<uint16_t*>(dsm);             // 128 x SA
        uint16_t* Ab1 = reinterpret_cast<uint16_t*>(dsm + ABUF);      // 128 x SA
        uint16_t* Vs  = reinterpret_cast<uint16_t*>(dsm + VS_OFF);    // 64 x SA

        // build Vs from g_hs + g_nrm (normalize + bf16 + transpose)
        if (tid < 64) s_rinv[tid] = rsqrtf(__ldcg(&g_nrm[bank][tid]));
        __syncthreads();
        {
            const float* hsrc = g_hs[bank];
#pragma unroll 8
            for (int it = 0; it < 32; it++) {
                const int i = it * 256 + tid;
                const int d = i >> 6, b = i & 63;
                const float v = __ldcg(&hsrc[i]) * s_rinv[b];
                const __nv_bfloat16 hv = __float2bfloat16(v);
                Vs[b * SA + d] = *reinterpret_cast<const uint16_t*>(&hv);
            }
        }

        const uint32_t v_base = (uint32_t)__cvta_generic_to_shared(Vs);
        const int b_row = lr + ((q >> 1) << 3);
        const int b_kh  = (q & 1) << 3;
        // A ldsm pattern (verified in P0): m16k16 fragment per k-step
        const int a_r = lr + ((q & 1) << 3);      // row within 16
        const int a_k = (q >> 1) << 3;            // k offset within 16
        uint32_t* Eb = reinterpret_cast<uint32_t*>(g_E[bank]);
        const int itcnt = (NTILE - 1 - bx) / NBB + 1;

        // coalesced row loader: one row per warp-instr (LDG.128), cvt, STS.64
#define LOADW(dstbuf, rbase, wv, t) {                                              \
            _Pragma("unroll")                                                      \
            for (int j = 0; j < 8; j++) {                                          \
                int rg = (rbase) + (wv) * 8 + j;                                   \
                rg = rg < NDATA ? rg : NDATA - 1;                                  \
                t[j] = __ldcs(reinterpret_cast<const float4*>(mem + (size_t)rg * FEAT) + lane); \
            } }
#define STOREW(dstbuf, wv, t) {                                                    \
            _Pragma("unroll")                                                      \
            for (int j = 0; j < 8; j++) {                                          \
                const int rl = warp * 16 + (wv) * 8 + j;                           \
                uint2 p;                                                           \
                p.x = pack_bf2(t[j].x, t[j].y);                                    \
                p.y = pack_bf2(t[j].z, t[j].w);                                    \
                *reinterpret_cast<uint2*>(&(dstbuf)[rl * SA + lane * 4]) = p;      \
            } }

        // prologue: stage tile bx into Ab0
        {
            const int rb = bx * RBLK + warp * 16;
            float4 t[8];
            LOADW(Ab0, rb, 0, t);
            STOREW(Ab0, 0, t);
            LOADW(Ab0, rb, 1, t);
            STOREW(Ab0, 1, t);
        }
        __syncthreads();

        for (int i = 0; i < itcnt; i++) {
            uint16_t* cur = (i & 1) ? Ab1 : Ab0;
            uint16_t* nxt = (i & 1) ? Ab0 : Ab1;
            const uint32_t a_base = (uint32_t)__cvta_generic_to_shared(cur);
            const int r_base = (bx + i * NBB) * RBLK;
            const bool hn = (i + 1) < itcnt;
            const int nrb = (bx + (i + 1) * NBB) * RBLK + warp * 16;

            float acc[8][4];
#pragma unroll
            for (int f = 0; f < 8; f++)
#pragma unroll
                for (int e = 0; e < 4; e++) acc[f][e] = 0.f;

            float4 t[8];
            if (hn) LOADW(nxt, nrb, 0, t);     // in flight over ksteps 0-3

#pragma unroll
            for (int ks = 0; ks < 4; ks++) {
                const int k0 = ks * 16;
                uint32_t a[4];
                ldsm_x4(a, a_base + (uint32_t)((warp * 16 + a_r) * SA + k0 + a_k) * 2u);
#pragma unroll
                for (int nt = 0; nt < 4; nt++) {
                    uint32_t bb[4];
                    ldsm_x4(bb, v_base + (uint32_t)((nt * 16 + b_row) * SA + k0 + b_kh) * 2u);
                    mma_bf16(acc[nt * 2 + 0], a, bb[0], bb[1]);
                    mma_bf16(acc[nt * 2 + 1], a, bb[2], bb[3]);
                }
            }
            if (hn) {
                STOREW(nxt, 0, t);
                LOADW(nxt, nrb, 1, t);         // in flight over ksteps 4-7
            }
#pragma unroll
            for (int ks = 4; ks < 8; ks++) {
                const int k0 = ks * 16;
                uint32_t a[4];
                ldsm_x4(a, a_base + (uint32_t)((warp * 16 + a_r) * SA + k0 + a_k) * 2u);
#pragma unroll
                for (int nt = 0; nt < 4; nt++) {
                    uint32_t bb[4];
                    ldsm_x4(bb, v_base + (uint32_t)((nt * 16 + b_row) * SA + k0 + b_kh) * 2u);
                    mma_bf16(acc[nt * 2 + 0], a, bb[0], bb[1]);
                    mma_bf16(acc[nt * 2 + 1], a, bb[2], bb[3]);
                }
            }

            // epilogue: exp(logit/T) -> bf16 E[r][b] (same as R11)
            const int row0 = r_base + warp * 16 + (lane >> 2);
            const int row1 = row0 + 8;
            const int cbase = (lane & 3) * 2;
#pragma unroll
            for (int f = 0; f < 8; f++) {
                const int c = (f >> 1) * 16 + (f & 1) * 8 + cbase;
                if (row0 < NDATA)
                    Eb[(size_t)row0 * (BATCH / 2) + (c >> 1)] =
                        pack_bf2(__expf(acc[f][0] * NCE_T_INV), __expf(acc[f][1] * NCE_T_INV));
                if (row1 < NDATA)
                    Eb[(size_t)row1 * (BATCH / 2) + (c >> 1)] =
                        pack_bf2(__expf(acc[f][2] * NCE_T_INV), __expf(acc[f][3] * NCE_T_INV));
            }
            if (hn) STOREW(nxt, 1, t);
            __syncthreads();    // all warps done reading cur + writing nxt
        }
#undef LOADW
#undef STOREW
    }
    gbar(2, u);

    // ---------------- P3: gather into registers + per-block Z slot ----------------
    const int pbase = bx * 256 + tid;
    float gv[GITER];
    {
#pragma unroll
        for (int i = 0; i < GITER; i++) {
            const int p = pbase + i * GSTRIDE;
            gv[i] = 0.f;
            if (p < NPAIR) {
                const int s = __ldg(&samp[p]);
                const int b = p / NSAMP;
                gv[i] = ld_e_cg(&g_E[bank][(size_t)s * BATCH + b]);
            }
        }
        float lsum = 0.f;
#pragma unroll
        for (int i = 0; i < GITER; i++) lsum += gv[i];
#pragma unroll
        for (int o = 16; o; o >>= 1) lsum += __shfl_xor_sync(0xffffffffu, lsum, o);
        if ((tid & 31) == 0) s_red[tid >> 5] = lsum;
        __syncthreads();
        if (tid == 0) {
            double tot = 0.0;
#pragma unroll
            for (int i = 0; i < 8; i++) tot += (double)s_red[i];
            g_Zp[bank][bx] = (float)tot;
        }
    }
    gbar(3, u);

    // each block reduces its bank's Z slots
    {
        float zv = (tid < NBB) ? *(volatile float*)&g_Zp[bank][tid] : 0.f;
#pragma unroll
        for (int o = 16; o; o >>= 1) zv += __shfl_xor_sync(0xffffffffu, zv, o);
        if (lane == 0) s_red[warp] = zv;
        __syncthreads();
        if (tid == 0) {
            float zt = 0.f;
#pragma unroll
            for (int i = 0; i < 8; i++) zt += s_red[i];
            s_z = (float)((double)zt * ((double)NDATA / (double)NPAIR));
        }
        __syncthreads();
    }

    // ---------------- P4: loss from registers (batched logs) ----------------
    {
        const float zinv = 1.0f / s_z;
        float lsum = 0.f;
        float pn = 1.f, pd = 1.f;
#pragma unroll
        for (int i = 0; i < GITER; i++) {
            const int p = pbase + i * GSTRIDE;
            if (p < NPAIR) {
                const float x = gv[i] * zinv;
                const int b = p / NSAMP;
                const bool pos = (p - b * NSAMP) == 0;
                pn *= pos ? x : M_CONST;
                pd *= x + M_CONST + EPS_C;
            }
            if (i == 13 || i == GITER - 1) {
                lsum += __logf(pn / pd);
                pn = 1.f; pd = 1.f;
            }
        }
#pragma unroll
        for (int o = 16; o; o >>= 1) lsum += __shfl_xor_sync(0xffffffffu, lsum, o);
        __syncthreads();
        if ((tid & 31) == 0) s_red[tid >> 5] = lsum;
        __syncthreads();
        if (tid == 0) {
            double tot = 0.0;
#pragma unroll
            for (int i = 0; i < 8; i++) tot += (double)s_red[i];
            g_Lp[u] = (float)tot;
            __threadfence();
            atomicAdd(&g_bars[4][u & 7], 1);
        }
    }

    // ---------------- block 0: finalize + reset ----------------
    if (u == 0) {
        if (tid == 0) {
            while (bar_sum(4) < NB) __nanosleep(64);
        }
        __syncthreads();
        double s = 0.0;
        if (tid < NB) s = (double)*(volatile float*)&g_Lp[tid];
        if (tid + 256 < NB) s += (double)*(volatile float*)&g_Lp[tid + 256];
#pragma unroll
        for (int o = 16; o; o >>= 1) s += __shfl_down_sync(0xffffffffu, s, o);
        if (lane == 0) s_dd[warp] = s;
        __syncthreads();
        if (tid == 0) {
            double t = 0.0;
#pragma unroll
            for (int i = 0; i < 8; i++) t += s_dd[i];
            out[0] = (float)(-t / (double)BATCH);
        }
        // reset barrier shards + norm accumulators for the next graph replay
        if (tid < 40) g_bars[tid >> 3][tid & 7] = 0;
        if (tid < 128) g_nrm[tid >> 6][tid & 63] = 0.f;
        __threadfence();
    }
}

// ---------------- launcher ----------------
extern "C" void kernel_launch(void* const* d_in, const int* in_sizes, int n_in,
                              void* d_out, int out_size) {
    const float* feat_s     = (const float*)d_in[0];
    const float* feat_t     = (const float*)d_in[1];
    // d_in[2] = idx (unused; positives already in sample_idx[:,0])
    const int*   sample_idx = (const int*)d_in[3];
    const float* w_s        = (const float*)d_in[4];
    const float* b_s        = (const float*)d_in[5];
    const float* w_t        = (const float*)d_in[6];
    const float* b_t        = (const float*)d_in[7];
    const float* mem_v1     = (const float*)d_in[8];
    const float* mem_v2     = (const float*)d_in[9];
    float* out = (float*)d_out;

    cudaFuncSetAttribute(k_fused, cudaFuncAttributeMaxDynamicSharedMemorySize, SMEM_DYN);
    k_fused<<<NB, 256, SMEM_DYN>>>(feat_s, feat_t, sample_idx,
                                   w_s, b_s, w_t, b_t, mem_v1, mem_v2, out);
}